// round 7
// baseline (speedup 1.0000x reference)
#include <cuda_runtime.h>
#include <cuda_fp16.h>
#include <cstdint>

// D[b,o] = sum_ck A[b,ck] * W[o,ck] — GEMM M=256, N=1024, K=16384, fp32 I/O.
// fp16 operands, fp32 accumulate, mma.sync m16n8k16.
// CTA tile 128x128, 8 warps with 64x32 warp tiles (27% less LDSM traffic than
// 32x32), 256 threads, SPLITK=16 -> 256 CTAs -> 2 CTAs/SM residency,
// TILE_K=32 double-buffered smem, fused split-K reduction.
#define B_DIM   256
#define N_DIM   1024
#define K_DIM   16384
#define TILE_M  128
#define TILE_N  128
#define TILE_K  32
#define SPLITK  16
#define K_PER_CTA (K_DIM / SPLITK)       // 1024
#define NITER   (K_PER_CTA / TILE_K)     // 32
#define NTHREADS 256
#define NTILES  ((B_DIM / TILE_M) * (N_DIM / TILE_N))   // 16

// Smem rows: 32 halfs (64 B) padded to stride 80 B -> conflict-free ldmatrix.
#define ROW_HB   80
#define A_HB     (128 * ROW_HB)           // 10240 B
#define STAGE_HB (2 * A_HB)               // A + B = 20480 B
#define SMEM_BYTES (2 * STAGE_HB)         // 40960 B (static, < 48KB)

__device__ float g_part[SPLITK * B_DIM * N_DIM];
__device__ int   g_cnt[NTILES];           // zero-init; self-resetting per launch

__device__ __forceinline__ uint32_t smem_u32(const void* p) {
    uint32_t a;
    asm("{ .reg .u64 t; cvta.to.shared.u64 t, %1; cvt.u32.u64 %0, t; }" : "=r"(a) : "l"(p));
    return a;
}

__device__ __forceinline__ void ldmx4(uint32_t* r, uint32_t addr) {
    asm volatile("ldmatrix.sync.aligned.m8n8.x4.shared.b16 {%0,%1,%2,%3}, [%4];"
                 : "=r"(r[0]), "=r"(r[1]), "=r"(r[2]), "=r"(r[3]) : "r"(addr));
}

__device__ __forceinline__ void mma16816(float* d, const uint32_t* a, const uint32_t* b) {
    asm volatile(
        "mma.sync.aligned.m16n8k16.row.col.f32.f16.f16.f32 "
        "{%0,%1,%2,%3}, {%4,%5,%6,%7}, {%8,%9}, {%0,%1,%2,%3};"
        : "+f"(d[0]), "+f"(d[1]), "+f"(d[2]), "+f"(d[3])
        : "r"(a[0]), "r"(a[1]), "r"(a[2]), "r"(a[3]), "r"(b[0]), "r"(b[1]));
}

__device__ __forceinline__ uint2 pack4h(float4 v) {
    __half2 lo = __floats2half2_rn(v.x, v.y);
    __half2 hi = __floats2half2_rn(v.z, v.w);
    uint2 r;
    r.x = *(uint32_t*)&lo;
    r.y = *(uint32_t*)&hi;
    return r;
}

__global__ void __launch_bounds__(NTHREADS, 2)
StreamingConv_gemm_kernel(const float* __restrict__ A, const float* __restrict__ W,
                          float* __restrict__ out)
{
    __shared__ __align__(16) char smem[SMEM_BYTES];
    const uint32_t sb = smem_u32(smem);

    const int tid = threadIdx.x;
    const int lane = tid & 31;
    const int wid = tid >> 5;
    const int wm = wid >> 2;          // 0..1 -> 64-row band of M
    const int wn = wid & 3;           // 0..3 -> 32-col band of N

    const int m0 = blockIdx.y * TILE_M;
    const int n0 = blockIdx.x * TILE_N;
    const int sk = blockIdx.z;
    const size_t kbase = (size_t)sk * K_PER_CTA;

    // ---- gmem load mapping: A and B tiles are each 128 rows x 8 float4 ----
    // 1024 float4 / 256 threads = 4 per thread per tile.
    const float* pa[4];
    const float* pb[4];
    uint32_t s_off[4];
    #pragma unroll
    for (int i = 0; i < 4; i++) {
        const int idx = tid + NTHREADS * i;
        const int row = idx >> 3;     // 0..127
        const int c4  = idx & 7;
        pa[i] = A + (size_t)(m0 + row) * K_DIM + kbase + c4 * 4;
        pb[i] = W + (size_t)(n0 + row) * K_DIM + kbase + c4 * 4;
        s_off[i] = (uint32_t)(row * ROW_HB + c4 * 8);
    }

    // ---- ldmatrix per-lane tile offsets (add ks*32 at use) ----
    uint32_t a_off[4];
    #pragma unroll
    for (int mt = 0; mt < 4; mt++)
        a_off[mt] = (uint32_t)((wm * 64 + mt * 16 + (lane & 15)) * ROW_HB + (lane >> 4) * 16);
    uint32_t b_off[2];
    #pragma unroll
    for (int p = 0; p < 2; p++)
        b_off[p] = (uint32_t)(A_HB + (wn * 32 + (2 * p + (lane >> 4)) * 8 + (lane & 7)) * ROW_HB
                              + ((lane >> 3) & 1) * 16);

    float acc[4][4][4];
    #pragma unroll
    for (int mt = 0; mt < 4; mt++)
        #pragma unroll
        for (int nt = 0; nt < 4; nt++)
            #pragma unroll
            for (int j = 0; j < 4; j++) acc[mt][nt][j] = 0.f;

    // ---- prologue: chunk 0 -> stage 0 ----
    #pragma unroll
    for (int i = 0; i < 4; i++) {
        *(uint2*)(smem + s_off[i])        = pack4h(*(const float4*)pa[i]);
        *(uint2*)(smem + A_HB + s_off[i]) = pack4h(*(const float4*)pb[i]);
    }
    __syncthreads();

    #pragma unroll 2
    for (int it = 0; it < NITER; ++it) {
        // load + convert chunk it+1 (uint2 queue: 16 regs; cvt right after LDG)
        uint2 qa[4], qb[4];
        if (it + 1 < NITER) {
            const size_t ko = (size_t)(it + 1) * TILE_K;
            #pragma unroll
            for (int i = 0; i < 4; i++) qa[i] = pack4h(*(const float4*)(pa[i] + ko));
            #pragma unroll
            for (int i = 0; i < 4; i++) qb[i] = pack4h(*(const float4*)(pb[i] + ko));
        }

        // compute current tile from stage it&1 (two k16 steps)
        const uint32_t base = sb + (uint32_t)(it & 1) * STAGE_HB;
        #pragma unroll
        for (int ks = 0; ks < 2; ks++) {
            uint32_t afr[4][4], bfr[2][4];
            #pragma unroll
            for (int mt = 0; mt < 4; mt++) ldmx4(afr[mt], base + a_off[mt] + ks * 32);
            #pragma unroll
            for (int p = 0; p < 2; p++)  ldmx4(bfr[p], base + b_off[p] + ks * 32);
            #pragma unroll
            for (int mt = 0; mt < 4; mt++)
                #pragma unroll
                for (int nt = 0; nt < 4; nt++) {
                    uint32_t bb[2] = { bfr[nt >> 1][(nt & 1) * 2], bfr[nt >> 1][(nt & 1) * 2 + 1] };
                    mma16816(acc[mt][nt], afr[mt], bb);
                }
        }

        // store chunk it+1 into the other stage
        if (it + 1 < NITER) {
            const uint32_t nxt = (uint32_t)((it + 1) & 1) * STAGE_HB;
            #pragma unroll
            for (int i = 0; i < 4; i++) {
                *(uint2*)(smem + nxt + s_off[i])        = qa[i];
                *(uint2*)(smem + nxt + A_HB + s_off[i]) = qb[i];
            }
        }
        __syncthreads();
    }

    // ---- write split-K partials ----
    float* pbase = &g_part[(size_t)sk * (B_DIM * N_DIM)];
    #pragma unroll
    for (int mt = 0; mt < 4; mt++) {
        const int row0 = m0 + wm * 64 + mt * 16 + (lane >> 2);
        #pragma unroll
        for (int nt = 0; nt < 4; nt++) {
            const int col = n0 + wn * 32 + nt * 8 + 2 * (lane & 3);
            *(float2*)&pbase[(size_t)row0 * N_DIM + col]       = make_float2(acc[mt][nt][0], acc[mt][nt][1]);
            *(float2*)&pbase[(size_t)(row0 + 8) * N_DIM + col] = make_float2(acc[mt][nt][2], acc[mt][nt][3]);
        }
    }

    // ---- fused split-K reduction: last CTA per (m,n)-tile reduces ----
    __threadfence();
    __syncthreads();
    volatile int* flag = (volatile int*)smem;
    if (tid == 0) {
        const int t = blockIdx.y * gridDim.x + blockIdx.x;
        const int old = atomicAdd(&g_cnt[t], 1);
        *flag = (old == SPLITK - 1) ? 1 : 0;
        if (old == SPLITK - 1) g_cnt[t] = 0;   // self-reset for graph replay
    }
    __syncthreads();
    if (*flag) {
        __threadfence();   // acquire: make all partials visible
        // tile = 128 rows x 32 float4 = 4096 float4; 256 threads x 16 each
        #pragma unroll
        for (int i = 0; i < 16; i++) {
            const int j = tid + NTHREADS * i;
            const int rr = j >> 5;        // 0..127
            const int c4 = j & 31;
            const size_t off = (size_t)(m0 + rr) * N_DIM + n0 + c4 * 4;
            float4 accv = *(const float4*)&g_part[off];
            #pragma unroll
            for (int s = 1; s < SPLITK; s++) {
                const float4 v = *(const float4*)&g_part[(size_t)s * (B_DIM * N_DIM) + off];
                accv.x += v.x; accv.y += v.y; accv.z += v.z; accv.w += v.w;
            }
            *(float4*)&out[off] = accv;
        }
    }
}

extern "C" void kernel_launch(void* const* d_in, const int* in_sizes, int n_in,
                              void* d_out, int out_size)
{
    const float* A = (const float*)d_in[0];   // curr_input [256, 1024, 16]
    const float* W = (const float*)d_in[1];   // weight     [1024, 1024, 16]

    dim3 grid(N_DIM / TILE_N, B_DIM / TILE_M, SPLITK);   // (8, 2, 16) = 256 CTAs
    StreamingConv_gemm_kernel<<<grid, NTHREADS>>>(A, W, (float*)d_out);
}

// round 9
// speedup vs baseline: 1.2042x; 1.2042x over previous
#include <cuda_runtime.h>
#include <cuda_fp16.h>
#include <cstdint>

// D[b,o] = sum_ck A[b,ck] * W[o,ck] — GEMM M=256, N=1024, K=16384, fp32 I/O.
// fp16 operands (converted at STS), fp32 accumulate, mma.sync m16n8k16.
// EXACT R4 mainloop (measured best: 47.6us GEMM): 512 threads / 16 warps,
// 128x128 CTA tile, 32x32 warp tiles, TILE_K=32, double-buffered smem,
// 2-deep fp32 register staging. Added: fused split-K reduction (last CTA
// per output tile reduces; deterministic read order; counter self-resets).
#define B_DIM   256
#define N_DIM   1024
#define K_DIM   16384
#define TILE_M  128
#define TILE_N  128
#define TILE_K  32
#define SPLITK  8
#define K_PER_CTA (K_DIM / SPLITK)       // 2048
#define NITER   (K_PER_CTA / TILE_K)     // 64
#define NTHREADS 512
#define NTILES  ((B_DIM / TILE_M) * (N_DIM / TILE_N))   // 16

// Smem tile: 128 rows x 32 halfs (64 B), padded stride 80 B (16-aligned;
// 80*r mod 128 covers 8 distinct 16B banks -> conflict-free ldmatrix).
#define ROW_HB   80
#define TILE_HB  (128 * ROW_HB)           // 10240 B
#define STAGE_HB (2 * TILE_HB)            // A + B per stage
#define SMEM_BYTES (2 * STAGE_HB)         // double buffer = 40960 B

__device__ float g_part[SPLITK * B_DIM * N_DIM];
__device__ int   g_cnt[NTILES];           // zero-init; self-resetting per launch

__device__ __forceinline__ uint32_t smem_u32(const void* p) {
    uint32_t a;
    asm("{ .reg .u64 t; cvta.to.shared.u64 t, %1; cvt.u32.u64 %0, t; }" : "=r"(a) : "l"(p));
    return a;
}

__device__ __forceinline__ void ldmx4(uint32_t* r, uint32_t addr) {
    asm volatile("ldmatrix.sync.aligned.m8n8.x4.shared.b16 {%0,%1,%2,%3}, [%4];"
                 : "=r"(r[0]), "=r"(r[1]), "=r"(r[2]), "=r"(r[3]) : "r"(addr));
}

__device__ __forceinline__ void mma16816(float* d, const uint32_t* a, const uint32_t* b) {
    asm volatile(
        "mma.sync.aligned.m16n8k16.row.col.f32.f16.f16.f32 "
        "{%0,%1,%2,%3}, {%4,%5,%6,%7}, {%8,%9}, {%0,%1,%2,%3};"
        : "+f"(d[0]), "+f"(d[1]), "+f"(d[2]), "+f"(d[3])
        : "r"(a[0]), "r"(a[1]), "r"(a[2]), "r"(a[3]), "r"(b[0]), "r"(b[1]));
}

__device__ __forceinline__ uint2 pack4h(float4 v) {
    __half2 lo = __floats2half2_rn(v.x, v.y);
    __half2 hi = __floats2half2_rn(v.z, v.w);
    uint2 r;
    r.x = *(uint32_t*)&lo;
    r.y = *(uint32_t*)&hi;
    return r;
}

__global__ void __launch_bounds__(NTHREADS, 1)
StreamingConv_gemm_kernel(const float* __restrict__ A, const float* __restrict__ W,
                          float* __restrict__ out)
{
    __shared__ __align__(16) char smem[SMEM_BYTES];
    const uint32_t sb = smem_u32(smem);

    const int tid = threadIdx.x;
    const int lane = tid & 31;
    const int wid = tid >> 5;
    const int wm = wid >> 2;          // 0..3 -> 32-row band of M
    const int wn = wid & 3;           // 0..3 -> 32-col band of N

    const int m0 = blockIdx.y * TILE_M;
    const int n0 = blockIdx.x * TILE_N;
    const int sk = blockIdx.z;
    const size_t kbase = (size_t)sk * K_PER_CTA;

    // ---- gmem load mapping: 2 float4 for A + 2 for W per thread per iter ----
    const float* pa[2];
    const float* pb[2];
    uint32_t sts_off[2];
    #pragma unroll
    for (int i = 0; i < 2; i++) {
        const int idx = tid + NTHREADS * i;
        const int row = idx >> 3;     // 0..127
        const int c4  = idx & 7;      // float4 within 32-float row
        pa[i] = A + (size_t)(m0 + row) * K_DIM + kbase + c4 * 4;
        pb[i] = W + (size_t)(n0 + row) * K_DIM + kbase + c4 * 4;
        sts_off[i] = (uint32_t)(row * ROW_HB + c4 * 8);   // 4 halfs = 8 B
    }

    // ---- ldmatrix per-lane tile offsets (add ks*32 at use) ----
    uint32_t a_off[2];
    #pragma unroll
    for (int mt = 0; mt < 2; mt++)
        a_off[mt] = (uint32_t)((wm * 32 + mt * 16 + (lane & 15)) * ROW_HB + (lane >> 4) * 16);
    uint32_t b_off[2];
    #pragma unroll
    for (int p = 0; p < 2; p++)
        b_off[p] = (uint32_t)((wn * 32 + (2 * p + (lane >> 4)) * 8 + (lane & 7)) * ROW_HB
                              + ((lane >> 3) & 1) * 16);

    float acc[2][4][4];
    #pragma unroll
    for (int mt = 0; mt < 2; mt++)
        #pragma unroll
        for (int nt = 0; nt < 4; nt++)
            #pragma unroll
            for (int j = 0; j < 4; j++) acc[mt][nt][j] = 0.f;

    // ---- 2-deep register staging queue (raw fp32; cvt at STS) ----
    float4 qa[2][2], qb[2][2];
    #pragma unroll
    for (int d = 0; d < 2; d++) {
        const size_t ko = (size_t)d * TILE_K;
        #pragma unroll
        for (int i = 0; i < 2; i++) {
            qa[d][i] = *(const float4*)(pa[i] + ko);
            qb[d][i] = *(const float4*)(pb[i] + ko);
        }
    }
    #pragma unroll
    for (int i = 0; i < 2; i++) {
        *(uint2*)(smem + sts_off[i])           = pack4h(qa[0][i]);
        *(uint2*)(smem + TILE_HB + sts_off[i]) = pack4h(qb[0][i]);
    }
    __syncthreads();

    #pragma unroll 2
    for (int it = 0; it < NITER; ++it) {
        // LDG chunk it+2 into the slot holding chunk it (already stored last iter)
        if (it + 2 < NITER) {
            const size_t ko = (size_t)(it + 2) * TILE_K;
            const int d = it & 1;
            #pragma unroll
            for (int i = 0; i < 2; i++) {
                qa[d][i] = *(const float4*)(pa[i] + ko);
                qb[d][i] = *(const float4*)(pb[i] + ko);
            }
        }

        // compute current tile from stage it&1 (two k16 steps)
        const uint32_t baseA = sb + (uint32_t)(it & 1) * STAGE_HB;
        const uint32_t baseB = baseA + TILE_HB;
        #pragma unroll
        for (int ks = 0; ks < 2; ks++) {
            uint32_t afr[2][4], bfr[2][4];
            #pragma unroll
            for (int mt = 0; mt < 2; mt++) ldmx4(afr[mt], baseA + a_off[mt] + ks * 32);
            #pragma unroll
            for (int p = 0; p < 2; p++)  ldmx4(bfr[p], baseB + b_off[p] + ks * 32);
            #pragma unroll
            for (int mt = 0; mt < 2; mt++)
                #pragma unroll
                for (int nt = 0; nt < 4; nt++) {
                    uint32_t bb[2] = { bfr[nt >> 1][(nt & 1) * 2], bfr[nt >> 1][(nt & 1) * 2 + 1] };
                    mma16816(acc[mt][nt], afr[mt], bb);
                }
        }

        // convert + store chunk it+1 (loaded 1 full iter ago) into other stage
        if (it + 1 < NITER) {
            const uint32_t nxt = (uint32_t)((it + 1) & 1) * STAGE_HB;
            const int d = (it + 1) & 1;
            #pragma unroll
            for (int i = 0; i < 2; i++) {
                *(uint2*)(smem + nxt + sts_off[i])           = pack4h(qa[d][i]);
                *(uint2*)(smem + nxt + TILE_HB + sts_off[i]) = pack4h(qb[d][i]);
            }
        }
        __syncthreads();
    }

    // ---- write split-K partials ----
    float* pbase = &g_part[(size_t)sk * (B_DIM * N_DIM)];
    #pragma unroll
    for (int mt = 0; mt < 2; mt++) {
        const int row0 = m0 + wm * 32 + mt * 16 + (lane >> 2);
        #pragma unroll
        for (int nt = 0; nt < 4; nt++) {
            const int col = n0 + wn * 32 + nt * 8 + 2 * (lane & 3);
            *(float2*)&pbase[(size_t)row0 * N_DIM + col]       = make_float2(acc[mt][nt][0], acc[mt][nt][1]);
            *(float2*)&pbase[(size_t)(row0 + 8) * N_DIM + col] = make_float2(acc[mt][nt][2], acc[mt][nt][3]);
        }
    }

    // ---- fused split-K reduction: last CTA per (m,n)-tile reduces ----
    __threadfence();
    __syncthreads();
    volatile int* flag = (volatile int*)smem;
    if (tid == 0) {
        const int t = blockIdx.y * gridDim.x + blockIdx.x;
        const int old = atomicAdd(&g_cnt[t], 1);
        *flag = (old == SPLITK - 1) ? 1 : 0;
        if (old == SPLITK - 1) g_cnt[t] = 0;   // self-reset for graph replay
    }
    __syncthreads();
    if (*flag) {
        __threadfence();   // acquire: make all partials visible
        // tile = 128 rows x 32 float4 = 4096 float4; 512 threads x 8 each
        #pragma unroll
        for (int i = 0; i < 8; i++) {
            const int j = tid + NTHREADS * i;
            const int rr = j >> 5;        // 0..127
            const int c4 = j & 31;
            const size_t off = (size_t)(m0 + rr) * N_DIM + n0 + c4 * 4;
            float4 accv = *(const float4*)&g_part[off];
            #pragma unroll
            for (int s = 1; s < SPLITK; s++) {
                const float4 v = *(const float4*)&g_part[(size_t)s * (B_DIM * N_DIM) + off];
                accv.x += v.x; accv.y += v.y; accv.z += v.z; accv.w += v.w;
            }
            *(float4*)&out[off] = accv;
        }
    }
}

extern "C" void kernel_launch(void* const* d_in, const int* in_sizes, int n_in,
                              void* d_out, int out_size)
{
    const float* A = (const float*)d_in[0];   // curr_input [256, 1024, 16]
    const float* W = (const float*)d_in[1];   // weight     [1024, 1024, 16]

    dim3 grid(N_DIM / TILE_N, B_DIM / TILE_M, SPLITK);   // (8, 2, 8) = 128 CTAs
    StreamingConv_gemm_kernel<<<grid, NTHREADS>>>(A, W, (float*)d_out);
}